// round 16
// baseline (speedup 1.0000x reference)
#include <cuda_runtime.h>
#include <cuda_bf16.h>
#include <math.h>

#define N_NODES 50000
#define M_PAD   50048          // 391 * 128
#define DIM     128
#define HEADS   4
#define HD      512
#define N_EDGES 400000
#define ETOT    450000
#define LN_EPS  1e-5f
#define NEG_SLOPE 0.2f

// ---------------- scratch (device globals; zero-initialized) ---------------
__device__ float g_xl[(size_t)M_PAD * HD];
__device__ float g_xr[(size_t)M_PAD * HD];
__device__ float g_y1[(size_t)M_PAD * DIM];
__device__ __nv_bfloat16 g_xh [(size_t)M_PAD * DIM],   g_xlo[(size_t)M_PAD * DIM];
__device__ __nv_bfloat16 g_y1h[(size_t)M_PAD * DIM],   g_y1l[(size_t)M_PAD * DIM];
__device__ __nv_bfloat16 g_mh [(size_t)M_PAD * 2*DIM], g_ml [(size_t)M_PAD * 2*DIM];
__device__ __nv_bfloat16 g_Wlh[HD * DIM],  g_Wll[HD * DIM];
__device__ __nv_bfloat16 g_Wrh[HD * DIM],  g_Wrl[HD * DIM];
__device__ __nv_bfloat16 g_W1h[2*DIM*DIM], g_W1l[2*DIM*DIM];
__device__ __nv_bfloat16 g_W2h[DIM*2*DIM], g_W2l[DIM*2*DIM];
// CSR scratch
__device__ int g_off[N_NODES + 1];
__device__ int g_cur[N_NODES];
__device__ int g_csr[ETOT];
__device__ int g_bsum[64];

// ---------------- helpers --------------------------------------------------
__device__ __forceinline__ float wsum(float v) {
#pragma unroll
    for (int o = 16; o; o >>= 1) v += __shfl_xor_sync(0xffffffffu, v, o);
    return v;
}
__device__ __forceinline__ float gelu_exact(float v) {
    return 0.5f * v * (1.0f + erff(v * 0.70710678118654752f));
}
__device__ __forceinline__ float lrelu(float v) { return fmaxf(v, NEG_SLOPE * v); }
__device__ __forceinline__ void hl_split(float v, __nv_bfloat16& h, __nv_bfloat16& l) {
    h = __float2bfloat16(v);
    l = __float2bfloat16(v - __bfloat162float(h));
}

// ---------------- MMA / ldmatrix / cp.async primitives ---------------------
__device__ __forceinline__ void ldsm4(unsigned &r0, unsigned &r1, unsigned &r2,
                                      unsigned &r3, unsigned addr) {
    asm volatile("ldmatrix.sync.aligned.m8n8.x4.shared.b16 {%0,%1,%2,%3},[%4];"
                 : "=r"(r0), "=r"(r1), "=r"(r2), "=r"(r3) : "r"(addr));
}
__device__ __forceinline__ void mma16816(float* d, const unsigned* a, const unsigned* b) {
    asm volatile(
        "mma.sync.aligned.m16n8k16.row.col.f32.bf16.bf16.f32 "
        "{%0,%1,%2,%3},{%4,%5,%6,%7},{%8,%9},{%0,%1,%2,%3};"
        : "+f"(d[0]), "+f"(d[1]), "+f"(d[2]), "+f"(d[3])
        : "r"(a[0]), "r"(a[1]), "r"(a[2]), "r"(a[3]), "r"(b[0]), "r"(b[1]));
}
__device__ __forceinline__ void cpa16(unsigned d, const void* s) {
    asm volatile("cp.async.cg.shared.global [%0], [%1], 16;" :: "r"(d), "l"(s));
}
__device__ __forceinline__ void cpa_commit() { asm volatile("cp.async.commit_group;"); }
__device__ __forceinline__ void cpa_wait0()  { asm volatile("cp.async.wait_group 0;"); }

// ---------------- prep: all fp32->bf16 hi/lo conversions + csr deg init ----
#define NX  (N_NODES * DIM / 4)          // 1,600,000
#define NWL (HD * DIM / 4)               // 16,384
#define NW1 (2 * DIM * DIM / 4)          // 8,192
#define NPREP (NX + 2 * NWL + 2 * NW1)   // 1,649,152

__device__ __forceinline__ void conv4(const float* __restrict__ s,
                                      __nv_bfloat16* __restrict__ h,
                                      __nv_bfloat16* __restrict__ l, int i) {
    float4 v = ((const float4*)s)[i];
    __nv_bfloat16 h0, h1, h2, h3, l0, l1, l2, l3;
    hl_split(v.x, h0, l0); hl_split(v.y, h1, l1);
    hl_split(v.z, h2, l2); hl_split(v.w, h3, l3);
    ((__nv_bfloat162*)h)[i * 2]     = __halves2bfloat162(h0, h1);
    ((__nv_bfloat162*)h)[i * 2 + 1] = __halves2bfloat162(h2, h3);
    ((__nv_bfloat162*)l)[i * 2]     = __halves2bfloat162(l0, l1);
    ((__nv_bfloat162*)l)[i * 2 + 1] = __halves2bfloat162(l2, l3);
}

__global__ void prep(const float* __restrict__ x,  const float* __restrict__ Wl,
                     const float* __restrict__ Wr, const float* __restrict__ W1,
                     const float* __restrict__ W2)
{
    int i = blockIdx.x * blockDim.x + threadIdx.x;
    if (i < N_NODES) g_cur[i] = 1;          // self-loop pre-count
    if (i < NX) { conv4(x, g_xh, g_xlo, i); return; }
    i -= NX;
    if (i < NWL) { conv4(Wl, g_Wlh, g_Wll, i); return; }
    i -= NWL;
    if (i < NWL) { conv4(Wr, g_Wrh, g_Wrl, i); return; }
    i -= NWL;
    if (i < NW1) { conv4(W1, g_W1h, g_W1l, i); return; }
    i -= NW1;
    if (i < NW1) { conv4(W2, g_W2h, g_W2l, i); return; }
}

// ---------------- double-buffered bf16 hi/lo GEMM, BM=BN=128 ---------------
// NPASS=3: ah*bh+ah*bl+al*bh.  NPASS=2: ah*bh+ah*bl.
// EPI 0: bias->fp32   1: bias+gelu->bf16 hi/lo
// EPI 3: bias + residual R + LayerNorm(ln_g, ln_b) -> C (final out, row-guarded)
#define KC    32
#define PITCH 40
#define SA    (128 * PITCH)
#define ZP    132              // fp32 pitch for LN staging buffer

template <int NPASS, int EPI>
__global__ __launch_bounds__(256, 2)
void gemm_bf16(const __nv_bfloat16* __restrict__ Ah, const __nv_bfloat16* __restrict__ Al,
               const __nv_bfloat16* __restrict__ Bh, const __nv_bfloat16* __restrict__ Bl,
               const float* __restrict__ bias, const float* __restrict__ R,
               float* __restrict__ C, __nv_bfloat16* __restrict__ Chh,
               __nv_bfloat16* __restrict__ Cll,
               const float* __restrict__ ln_g, const float* __restrict__ ln_b,
               int Nn, int K)
{
    extern __shared__ __nv_bfloat16 smem[];
    __nv_bfloat16* sAh = smem;
    __nv_bfloat16* sAl = smem + 2 * SA;
    __nv_bfloat16* sBh = smem + 4 * SA;
    __nv_bfloat16* sBl = smem + 6 * SA;

    const int tid  = threadIdx.x;
    const int lane = tid & 31;
    const int warp = tid >> 5;
    const int wm = warp >> 1;
    const int wn = warp & 1;
    const int rb = blockIdx.x * 128, cb = blockIdx.y * 128;

    const int a_row = lane & 15;
    const int a_k   = (lane >> 4) << 3;
    const int b_n   = (lane & 7) + ((lane >> 4) << 3);
    const int b_k   = lane & 8;

    const unsigned uAh = (unsigned)__cvta_generic_to_shared(sAh);
    const unsigned uAl = (unsigned)__cvta_generic_to_shared(sAl);
    const unsigned uBh = (unsigned)__cvta_generic_to_shared(sBh);
    const unsigned uBl = (unsigned)__cvta_generic_to_shared(sBl);

    float acc[2][8][4];
#pragma unroll
    for (int i = 0; i < 2; i++)
#pragma unroll
        for (int j = 0; j < 8; j++)
#pragma unroll
            for (int q = 0; q < 4; q++) acc[i][j][q] = 0.0f;

    const int NCH = K / KC;

    auto issue = [&](int kc, int st) {
#pragma unroll
        for (int it = 0; it < 2; it++) {
            int i   = tid + it * 256;
            int row = i >> 2;
            int ac  = (i & 3) * 8;
            unsigned doff = (unsigned)((st * SA + row * PITCH + ac) * 2);
            size_t ga = (size_t)(rb + row) * K + kc + ac;
            size_t gb = (size_t)(cb + row) * K + kc + ac;
            cpa16(uAh + doff, Ah + ga);
            if (NPASS == 3) cpa16(uAl + doff, Al + ga);
            cpa16(uBh + doff, Bh + gb);
            cpa16(uBl + doff, Bl + gb);
        }
        cpa_commit();
    };

    issue(0, 0);

    for (int ch = 0; ch < NCH; ch++) {
        cpa_wait0();
        __syncthreads();
        if (ch + 1 < NCH) issue((ch + 1) * KC, (ch + 1) & 1);

        const int st = ch & 1;
#pragma unroll
        for (int s = 0; s < 2; s++) {
            unsigned ah[2][4], al[2][4];
#pragma unroll
            for (int mt = 0; mt < 2; mt++) {
                unsigned offA = (unsigned)(((st * SA) +
                    (wm * 32 + mt * 16 + a_row) * PITCH + s * 16 + a_k) * 2);
                ldsm4(ah[mt][0], ah[mt][1], ah[mt][2], ah[mt][3], uAh + offA);
                if (NPASS == 3)
                    ldsm4(al[mt][0], al[mt][1], al[mt][2], al[mt][3], uAl + offA);
            }
#pragma unroll
            for (int nt = 0; nt < 4; nt++) {
                unsigned offB = (unsigned)(((st * SA) +
                    (wn * 64 + nt * 16 + b_n) * PITCH + s * 16 + b_k) * 2);
                unsigned bh[4], bl[4];
                ldsm4(bh[0], bh[1], bh[2], bh[3], uBh + offB);
                ldsm4(bl[0], bl[1], bl[2], bl[3], uBl + offB);
#pragma unroll
                for (int mt = 0; mt < 2; mt++) {
                    mma16816(acc[mt][nt * 2 + 0], ah[mt], &bh[0]);
                    mma16816(acc[mt][nt * 2 + 0], ah[mt], &bl[0]);
                    if (NPASS == 3) mma16816(acc[mt][nt * 2 + 0], al[mt], &bh[0]);
                    mma16816(acc[mt][nt * 2 + 1], ah[mt], &bh[2]);
                    mma16816(acc[mt][nt * 2 + 1], ah[mt], &bl[2]);
                    if (NPASS == 3) mma16816(acc[mt][nt * 2 + 1], al[mt], &bh[2]);
                }
            }
        }
        __syncthreads();
    }

    if (EPI == 3) {
        // stage z = acc + bias + R into smem (pipeline stages now idle), then LN
        float* zbuf = (float*)smem;      // 128 x ZP fp32 = 67.6 KB < 80 KB
#pragma unroll
        for (int mt = 0; mt < 2; mt++) {
#pragma unroll
            for (int jj = 0; jj < 8; jj++) {
                int lrow0 = wm * 32 + mt * 16 + (lane >> 2);
                int col   = wn * 64 + jj * 8 + ((lane & 3) << 1);
                float2 bi = *(const float2*)&bias[col];
#pragma unroll
                for (int half = 0; half < 2; half++) {
                    int lrow = lrow0 + half * 8;
                    float2 r = *(const float2*)&R[(size_t)(rb + lrow) * Nn + col];
                    zbuf[lrow * ZP + col]     = acc[mt][jj][half * 2 + 0] + bi.x + r.x;
                    zbuf[lrow * ZP + col + 1] = acc[mt][jj][half * 2 + 1] + bi.y + r.y;
                }
            }
        }
        __syncthreads();
        // warp w handles rows w*16 .. w*16+15
        for (int rr = 0; rr < 16; rr++) {
            int lrow = warp * 16 + rr;
            int grow = rb + lrow;
            float4 v = *(const float4*)&zbuf[lrow * ZP + lane * 4];
            float mu = wsum(v.x + v.y + v.z + v.w) * (1.0f / DIM);
            float dx = v.x - mu, dy = v.y - mu, dz = v.z - mu, dw = v.w - mu;
            float var = wsum(dx * dx + dy * dy + dz * dz + dw * dw) * (1.0f / DIM);
            float rstd = rsqrtf(var + LN_EPS);
            float4 g = ((const float4*)ln_g)[lane];
            float4 b = ((const float4*)ln_b)[lane];
            float4 o;
            o.x = dx * rstd * g.x + b.x;  o.y = dy * rstd * g.y + b.y;
            o.z = dz * rstd * g.z + b.z;  o.w = dw * rstd * g.w + b.w;
            if (grow < N_NODES)
                *(float4*)&C[(size_t)grow * DIM + lane * 4] = o;
        }
        return;
    }

#pragma unroll
    for (int mt = 0; mt < 2; mt++) {
#pragma unroll
        for (int jj = 0; jj < 8; jj++) {
            int row0 = rb + wm * 32 + mt * 16 + (lane >> 2);
            int col  = cb + wn * 64 + jj * 8 + ((lane & 3) << 1);
            float2 bi = *(const float2*)&bias[col];
#pragma unroll
            for (int half = 0; half < 2; half++) {
                int row = row0 + half * 8;
                float v0 = acc[mt][jj][half * 2 + 0] + bi.x;
                float v1 = acc[mt][jj][half * 2 + 1] + bi.y;
                if (EPI == 1) {
                    v0 = gelu_exact(v0); v1 = gelu_exact(v1);
                    __nv_bfloat16 h0, h1, l0, l1;
                    hl_split(v0, h0, l0); hl_split(v1, h1, l1);
                    *(__nv_bfloat162*)&Chh[(size_t)row * Nn + col] = __halves2bfloat162(h0, h1);
                    *(__nv_bfloat162*)&Cll[(size_t)row * Nn + col] = __halves2bfloat162(l0, l1);
                } else {
                    *(float2*)&C[(size_t)row * Nn + col] = make_float2(v0, v1);
                }
            }
        }
    }
}

// ================= CSR build ================================================
__global__ void csr_hist(const int* __restrict__ ei)
{
    int e = blockIdx.x * blockDim.x + threadIdx.x;
    if (e < N_EDGES) atomicAdd(&g_cur[ei[N_EDGES + e]], 1);
}
__global__ __launch_bounds__(1024)
void csr_scan1()
{
    int tid = threadIdx.x, lane = tid & 31, warp = tid >> 5;
    int idx = blockIdx.x * 1024 + tid;
    int val = (idx < N_NODES) ? g_cur[idx] : 0;
    int v = val;
#pragma unroll
    for (int o = 1; o < 32; o <<= 1) {
        int t = __shfl_up_sync(0xffffffffu, v, o);
        if (lane >= o) v += t;
    }
    __shared__ int ws[32];
    if (lane == 31) ws[warp] = v;
    __syncthreads();
    if (warp == 0) {
        int w = ws[lane];
#pragma unroll
        for (int o = 1; o < 32; o <<= 1) {
            int t = __shfl_up_sync(0xffffffffu, w, o);
            if (lane >= o) w += t;
        }
        ws[lane] = w;
    }
    __syncthreads();
    int incl = v + (warp ? ws[warp - 1] : 0);
    if (idx < N_NODES) g_off[idx] = incl - val;
    if (tid == 1023) g_bsum[blockIdx.x] = incl;
}
__global__ void csr_scan23(int nblk)
{
    __shared__ int ps[64];
    if (threadIdx.x == 0) {
        int run = 0;
        for (int b = 0; b < nblk; b++) { ps[b] = run; run += g_bsum[b]; }
    }
    __syncthreads();
    int idx = blockIdx.x * blockDim.x + threadIdx.x;
    if (idx < N_NODES) {
        int o = g_off[idx] + ps[idx >> 10];
        g_off[idx] = o;
        g_cur[idx] = o;
    }
    if (idx == 0) g_off[N_NODES] = ETOT;
}
__global__ void csr_scatter(const int* __restrict__ ei)
{
    int id = blockIdx.x * blockDim.x + threadIdx.x;
    if (id < N_NODES) {
        int pos = atomicAdd(&g_cur[id], 1);
        g_csr[pos] = id;
    } else if (id < N_NODES + N_EDGES) {
        int e = id - N_NODES;
        int src = ei[e], dst = ei[N_EDGES + e];
        int pos = atomicAdd(&g_cur[dst], 1);
        g_csr[pos] = src;
    }
}

// ================= fused GAT (pairwise online softmax, att in smem) =========
// __launch_bounds__(256, 2): cap regs at 128 (no spills at ~100-reg footprint)
// while guaranteeing 2 blocks/SM — the R14 regression was ptxas exceeding 128
// regs and dropping to 1 block/SM.
__global__ __launch_bounds__(256, 2)
void gat_fused(const float* __restrict__ x, const float* __restrict__ att,
               const float* __restrict__ bias, const float* __restrict__ g1,
               const float* __restrict__ be1)
{
    __shared__ float4 s_at[HEADS * 32];
    if (threadIdx.x < HEADS * 32)
        s_at[threadIdx.x] = ((const float4*)att)[threadIdx.x];
    __syncthreads();

    int node = (blockIdx.x * blockDim.x + threadIdx.x) >> 5;
    int lane = threadIdx.x & 31;
    if (node >= N_NODES) return;

    const float4* xrp = (const float4*)(g_xr + (size_t)node * HD);
    float4 xr4[HEADS];
#pragma unroll
    for (int h = 0; h < HEADS; h++) xr4[h] = xrp[h * 32 + lane];

    float m[HEADS], s[HEADS];
    float4 acc[HEADS];
#pragma unroll
    for (int h = 0; h < HEADS; h++) {
        m[h] = -INFINITY; s[h] = 0.0f;
        acc[h] = make_float4(0.f, 0.f, 0.f, 0.f);
    }

    const int beg = g_off[node], end = g_off[node + 1];
    int j = beg;
    for (; j + 2 <= end; j += 2) {
        int s0 = __ldg(&g_csr[j]);
        int s1 = __ldg(&g_csr[j + 1]);
        const float4* p0 = (const float4*)(g_xl + (size_t)s0 * HD);
        const float4* p1 = (const float4*)(g_xl + (size_t)s1 * HD);
        float4 v0[HEADS], v1[HEADS];
        float  e0[HEADS], e1[HEADS];
#pragma unroll
        for (int h = 0; h < HEADS; h++) {
            v0[h] = __ldg(&p0[h * 32 + lane]);
            v1[h] = __ldg(&p1[h * 32 + lane]);
        }
#pragma unroll
        for (int h = 0; h < HEADS; h++) {
            float4 t = s_at[h * 32 + lane], r = xr4[h];
            float4 a = v0[h], b = v1[h];
            e0[h] = lrelu(a.x + r.x) * t.x + lrelu(a.y + r.y) * t.y
                  + lrelu(a.z + r.z) * t.z + lrelu(a.w + r.w) * t.w;
            e1[h] = lrelu(b.x + r.x) * t.x + lrelu(b.y + r.y) * t.y
                  + lrelu(b.z + r.z) * t.z + lrelu(b.w + r.w) * t.w;
        }
#pragma unroll
        for (int o = 16; o; o >>= 1) {
#pragma unroll
            for (int h = 0; h < HEADS; h++) {
                e0[h] += __shfl_xor_sync(0xffffffffu, e0[h], o);
                e1[h] += __shfl_xor_sync(0xffffffffu, e1[h], o);
            }
        }
#pragma unroll
        for (int h = 0; h < HEADS; h++) {
            float mn = fmaxf(m[h], fmaxf(e0[h], e1[h]));
            float sc = __expf(m[h] - mn);
            float q0 = __expf(e0[h] - mn);
            float q1 = __expf(e1[h] - mn);
            s[h] = s[h] * sc + q0 + q1;
            acc[h].x = acc[h].x * sc + q0 * v0[h].x + q1 * v1[h].x;
            acc[h].y = acc[h].y * sc + q0 * v0[h].y + q1 * v1[h].y;
            acc[h].z = acc[h].z * sc + q0 * v0[h].z + q1 * v1[h].z;
            acc[h].w = acc[h].w * sc + q0 * v0[h].w + q1 * v1[h].w;
            m[h] = mn;
        }
    }
    if (j < end) {
        int s0 = __ldg(&g_csr[j]);
        const float4* p0 = (const float4*)(g_xl + (size_t)s0 * HD);
        float4 v0[HEADS];
        float  e0[HEADS];
#pragma unroll
        for (int h = 0; h < HEADS; h++) {
            v0[h] = __ldg(&p0[h * 32 + lane]);
            float4 t = s_at[h * 32 + lane], r = xr4[h], a = v0[h];
            e0[h] = lrelu(a.x + r.x) * t.x + lrelu(a.y + r.y) * t.y
                  + lrelu(a.z + r.z) * t.z + lrelu(a.w + r.w) * t.w;
        }
#pragma unroll
        for (int o = 16; o; o >>= 1)
#pragma unroll
            for (int h = 0; h < HEADS; h++)
                e0[h] += __shfl_xor_sync(0xffffffffu, e0[h], o);
#pragma unroll
        for (int h = 0; h < HEADS; h++) {
            float mn = fmaxf(m[h], e0[h]);
            float sc = __expf(m[h] - mn);
            float q0 = __expf(e0[h] - mn);
            s[h] = s[h] * sc + q0;
            acc[h].x = acc[h].x * sc + q0 * v0[h].x;
            acc[h].y = acc[h].y * sc + q0 * v0[h].y;
            acc[h].z = acc[h].z * sc + q0 * v0[h].z;
            acc[h].w = acc[h].w * sc + q0 * v0[h].w;
            m[h] = mn;
        }
    }

    float4 o4 = make_float4(0.f, 0.f, 0.f, 0.f);
#pragma unroll
    for (int h = 0; h < HEADS; h++) {
        float inv = 0.25f / (s[h] + 1e-16f);
        o4.x += acc[h].x * inv; o4.y += acc[h].y * inv;
        o4.z += acc[h].z * inv; o4.w += acc[h].w * inv;
    }
    float4 xb = ((const float4*)x)[(size_t)node * 32 + lane];
    float4 b4 = ((const float4*)bias)[lane];
    float4 v;
    v.x = xb.x + o4.x + b4.x;  v.y = xb.y + o4.y + b4.y;
    v.z = xb.z + o4.z + b4.z;  v.w = xb.w + o4.w + b4.w;

    float mu = wsum(v.x + v.y + v.z + v.w) * (1.0f / DIM);
    float dx = v.x - mu, dy = v.y - mu, dz = v.z - mu, dw = v.w - mu;
    float var = wsum(dx * dx + dy * dy + dz * dz + dw * dw) * (1.0f / DIM);
    float rstd = rsqrtf(var + LN_EPS);
    float4 g = ((const float4*)g1)[lane];
    float4 b = ((const float4*)be1)[lane];
    float4 o;
    o.x = dx * rstd * g.x + b.x;  o.y = dy * rstd * g.y + b.y;
    o.z = dz * rstd * g.z + b.z;  o.w = dw * rstd * g.w + b.w;
    ((float4*)g_y1)[(size_t)node * 32 + lane] = o;

    __nv_bfloat16 h0, h1, h2, h3, l0, l1, l2, l3;
    hl_split(o.x, h0, l0); hl_split(o.y, h1, l1);
    hl_split(o.z, h2, l2); hl_split(o.w, h3, l3);
    size_t base = (size_t)node * 64 + lane * 2;
    ((__nv_bfloat162*)g_y1h)[base]     = __halves2bfloat162(h0, h1);
    ((__nv_bfloat162*)g_y1h)[base + 1] = __halves2bfloat162(h2, h3);
    ((__nv_bfloat162*)g_y1l)[base]     = __halves2bfloat162(l0, l1);
    ((__nv_bfloat162*)g_y1l)[base + 1] = __halves2bfloat162(l2, l3);
}

// ---------------- launch -----------------------------------------------------
extern "C" void kernel_launch(void* const* d_in, const int* in_sizes, int n_in,
                              void* d_out, int out_size)
{
    const float* x    = (const float*)d_in[0];
    const int*   ei   = (const int*)d_in[1];
    const float* Wl   = (const float*)d_in[2];
    const float* bl   = (const float*)d_in[3];
    const float* Wr   = (const float*)d_in[4];
    const float* br   = (const float*)d_in[5];
    const float* att  = (const float*)d_in[6];
    const float* bias = (const float*)d_in[7];
    const float* g1   = (const float*)d_in[8];
    const float* be1  = (const float*)d_in[9];
    const float* W1   = (const float*)d_in[10];
    const float* b1   = (const float*)d_in[11];
    const float* W2   = (const float*)d_in[12];
    const float* b2   = (const float*)d_in[13];
    const float* g2   = (const float*)d_in[14];
    const float* be2  = (const float*)d_in[15];
    float* out = (float*)d_out;

    float *p_xl, *p_xr, *p_y1;
    __nv_bfloat16 *p_xh, *p_xlo, *p_y1h, *p_y1l, *p_mh, *p_ml;
    __nv_bfloat16 *p_Wlh, *p_Wll, *p_Wrh, *p_Wrl, *p_W1h, *p_W1l, *p_W2h, *p_W2l;
    cudaGetSymbolAddress((void**)&p_xl,  g_xl);
    cudaGetSymbolAddress((void**)&p_xr,  g_xr);
    cudaGetSymbolAddress((void**)&p_y1,  g_y1);
    cudaGetSymbolAddress((void**)&p_xh,  g_xh);
    cudaGetSymbolAddress((void**)&p_xlo, g_xlo);
    cudaGetSymbolAddress((void**)&p_y1h, g_y1h);
    cudaGetSymbolAddress((void**)&p_y1l, g_y1l);
    cudaGetSymbolAddress((void**)&p_mh,  g_mh);
    cudaGetSymbolAddress((void**)&p_ml,  g_ml);
    cudaGetSymbolAddress((void**)&p_Wlh, g_Wlh);
    cudaGetSymbolAddress((void**)&p_Wll, g_Wll);
    cudaGetSymbolAddress((void**)&p_Wrh, g_Wrh);
    cudaGetSymbolAddress((void**)&p_Wrl, g_Wrl);
    cudaGetSymbolAddress((void**)&p_W1h, g_W1h);
    cudaGetSymbolAddress((void**)&p_W1l, g_W1l);
    cudaGetSymbolAddress((void**)&p_W2h, g_W2h);
    cudaGetSymbolAddress((void**)&p_W2l, g_W2l);

    const int SMEM = 8 * SA * 2;   // 81920 bytes
    cudaFuncSetAttribute(gemm_bf16<3, 0>, cudaFuncAttributeMaxDynamicSharedMemorySize, SMEM);
    cudaFuncSetAttribute(gemm_bf16<2, 0>, cudaFuncAttributeMaxDynamicSharedMemorySize, SMEM);
    cudaFuncSetAttribute(gemm_bf16<3, 1>, cudaFuncAttributeMaxDynamicSharedMemorySize, SMEM);
    cudaFuncSetAttribute(gemm_bf16<3, 3>, cudaFuncAttributeMaxDynamicSharedMemorySize, SMEM);

    const int MB = M_PAD / 128;                 // 391
    const int SNBLK = (N_NODES + 1023) / 1024;  // 49

    prep<<<(NPREP + 255) / 256, 256>>>(x, Wl, Wr, W1, W2);

    csr_hist<<<(N_EDGES + 255) / 256, 256>>>(ei);
    csr_scan1<<<SNBLK, 1024>>>();
    csr_scan23<<<(N_NODES + 255) / 256, 256>>>(SNBLK);
    csr_scatter<<<(N_NODES + N_EDGES + 255) / 256, 256>>>(ei);

    // xl = x @ Wl^T + bl  (3-pass: feeds aggregation)
    gemm_bf16<3, 0><<<dim3(MB, HD / 128), 256, SMEM>>>(p_xh, p_xlo, p_Wlh, p_Wll, bl,
                                                       nullptr, p_xl, nullptr, nullptr,
                                                       nullptr, nullptr, HD, DIM);
    // xr = x @ Wr^T + br  (2-pass: logits only)
    gemm_bf16<2, 0><<<dim3(MB, HD / 128), 256, SMEM>>>(p_xh, nullptr, p_Wrh, p_Wrl, br,
                                                       nullptr, p_xr, nullptr, nullptr,
                                                       nullptr, nullptr, HD, DIM);

    gat_fused<<<(N_NODES * 32 + 255) / 256, 256>>>(x, att, bias, g1, be1);

    // mid = gelu(y1 @ W1^T + b1) -> bf16 hi/lo
    gemm_bf16<3, 1><<<dim3(MB, (2 * DIM) / 128), 256, SMEM>>>(p_y1h, p_y1l, p_W1h, p_W1l, b1,
                                                              nullptr, nullptr, p_mh, p_ml,
                                                              nullptr, nullptr, 2 * DIM, DIM);
    // out = LN2(mid @ W2^T + b2 + y1)  (fused epilogue, writes final output)
    gemm_bf16<3, 3><<<dim3(MB, 1), 256, SMEM>>>(p_mh, p_ml, p_W2h, p_W2l, b2,
                                                p_y1, out, nullptr, nullptr,
                                                g2, be2, DIM, 2 * DIM);
}

// round 17
// speedup vs baseline: 1.4380x; 1.4380x over previous
#include <cuda_runtime.h>
#include <cuda_bf16.h>
#include <math.h>

#define N_NODES 50000
#define M_PAD   50048          // 391 * 128
#define DIM     128
#define HEADS   4
#define HD      512
#define N_EDGES 400000
#define ETOT    450000
#define LN_EPS  1e-5f
#define NEG_SLOPE 0.2f

// ---------------- scratch (device globals; zero-initialized) ---------------
__device__ float g_xl[(size_t)M_PAD * HD];
__device__ float g_xr[(size_t)M_PAD * HD];
__device__ float g_y1[(size_t)M_PAD * DIM];
__device__ __nv_bfloat16 g_xh [(size_t)M_PAD * DIM],   g_xlo[(size_t)M_PAD * DIM];
__device__ __nv_bfloat16 g_y1h[(size_t)M_PAD * DIM],   g_y1l[(size_t)M_PAD * DIM];
__device__ __nv_bfloat16 g_mh [(size_t)M_PAD * 2*DIM], g_ml [(size_t)M_PAD * 2*DIM];
__device__ __nv_bfloat16 g_Wlh[HD * DIM],  g_Wll[HD * DIM];
__device__ __nv_bfloat16 g_Wrh[HD * DIM],  g_Wrl[HD * DIM];
__device__ __nv_bfloat16 g_W1h[2*DIM*DIM], g_W1l[2*DIM*DIM];
__device__ __nv_bfloat16 g_W2h[DIM*2*DIM], g_W2l[DIM*2*DIM];
// CSR scratch
__device__ int g_off[N_NODES + 1];
__device__ int g_cur[N_NODES];
__device__ int g_csr[ETOT];
__device__ int g_bsum[64];

// ---------------- helpers --------------------------------------------------
__device__ __forceinline__ float wsum(float v) {
#pragma unroll
    for (int o = 16; o; o >>= 1) v += __shfl_xor_sync(0xffffffffu, v, o);
    return v;
}
__device__ __forceinline__ float gelu_exact(float v) {
    return 0.5f * v * (1.0f + erff(v * 0.70710678118654752f));
}
__device__ __forceinline__ float lrelu(float v) { return fmaxf(v, NEG_SLOPE * v); }
__device__ __forceinline__ void hl_split(float v, __nv_bfloat16& h, __nv_bfloat16& l) {
    h = __float2bfloat16(v);
    l = __float2bfloat16(v - __bfloat162float(h));
}

// ---------------- MMA / ldmatrix / cp.async primitives ---------------------
__device__ __forceinline__ void ldsm4(unsigned &r0, unsigned &r1, unsigned &r2,
                                      unsigned &r3, unsigned addr) {
    asm volatile("ldmatrix.sync.aligned.m8n8.x4.shared.b16 {%0,%1,%2,%3},[%4];"
                 : "=r"(r0), "=r"(r1), "=r"(r2), "=r"(r3) : "r"(addr));
}
__device__ __forceinline__ void mma16816(float* d, const unsigned* a, const unsigned* b) {
    asm volatile(
        "mma.sync.aligned.m16n8k16.row.col.f32.bf16.bf16.f32 "
        "{%0,%1,%2,%3},{%4,%5,%6,%7},{%8,%9},{%0,%1,%2,%3};"
        : "+f"(d[0]), "+f"(d[1]), "+f"(d[2]), "+f"(d[3])
        : "r"(a[0]), "r"(a[1]), "r"(a[2]), "r"(a[3]), "r"(b[0]), "r"(b[1]));
}
__device__ __forceinline__ void cpa16(unsigned d, const void* s) {
    asm volatile("cp.async.cg.shared.global [%0], [%1], 16;" :: "r"(d), "l"(s));
}
__device__ __forceinline__ void cpa_commit() { asm volatile("cp.async.commit_group;"); }
__device__ __forceinline__ void cpa_wait0()  { asm volatile("cp.async.wait_group 0;"); }

// ---------------- prep: all fp32->bf16 hi/lo conversions + csr deg init ----
#define NX  (N_NODES * DIM / 4)          // 1,600,000
#define NWL (HD * DIM / 4)               // 16,384
#define NW1 (2 * DIM * DIM / 4)          // 8,192
#define NPREP (NX + 2 * NWL + 2 * NW1)   // 1,649,152

__device__ __forceinline__ void conv4(const float* __restrict__ s,
                                      __nv_bfloat16* __restrict__ h,
                                      __nv_bfloat16* __restrict__ l, int i) {
    float4 v = ((const float4*)s)[i];
    __nv_bfloat16 h0, h1, h2, h3, l0, l1, l2, l3;
    hl_split(v.x, h0, l0); hl_split(v.y, h1, l1);
    hl_split(v.z, h2, l2); hl_split(v.w, h3, l3);
    ((__nv_bfloat162*)h)[i * 2]     = __halves2bfloat162(h0, h1);
    ((__nv_bfloat162*)h)[i * 2 + 1] = __halves2bfloat162(h2, h3);
    ((__nv_bfloat162*)l)[i * 2]     = __halves2bfloat162(l0, l1);
    ((__nv_bfloat162*)l)[i * 2 + 1] = __halves2bfloat162(l2, l3);
}

__global__ void prep(const float* __restrict__ x,  const float* __restrict__ Wl,
                     const float* __restrict__ Wr, const float* __restrict__ W1,
                     const float* __restrict__ W2)
{
    int i = blockIdx.x * blockDim.x + threadIdx.x;
    if (i < N_NODES) g_cur[i] = 1;          // self-loop pre-count
    if (i < NX) { conv4(x, g_xh, g_xlo, i); return; }
    i -= NX;
    if (i < NWL) { conv4(Wl, g_Wlh, g_Wll, i); return; }
    i -= NWL;
    if (i < NWL) { conv4(Wr, g_Wrh, g_Wrl, i); return; }
    i -= NWL;
    if (i < NW1) { conv4(W1, g_W1h, g_W1l, i); return; }
    i -= NW1;
    if (i < NW1) { conv4(W2, g_W2h, g_W2l, i); return; }
}

// ---------------- double-buffered bf16 hi/lo GEMM, BM=BN=128 ---------------
// NPASS=3: ah*bh+ah*bl+al*bh.  NPASS=2: ah*bh+ah*bl.
// EPI 0: bias->fp32   1: bias+gelu->bf16 hi/lo
// EPI 3: bias + residual R + LayerNorm(ln_g, ln_b) -> C (final out, row-guarded)
#define KC    32
#define PITCH 40
#define SA    (128 * PITCH)
#define ZP    132              // fp32 pitch for LN staging buffer

template <int NPASS, int EPI>
__global__ __launch_bounds__(256, 2)
void gemm_bf16(const __nv_bfloat16* __restrict__ Ah, const __nv_bfloat16* __restrict__ Al,
               const __nv_bfloat16* __restrict__ Bh, const __nv_bfloat16* __restrict__ Bl,
               const float* __restrict__ bias, const float* __restrict__ R,
               float* __restrict__ C, __nv_bfloat16* __restrict__ Chh,
               __nv_bfloat16* __restrict__ Cll,
               const float* __restrict__ ln_g, const float* __restrict__ ln_b,
               int Nn, int K)
{
    extern __shared__ __nv_bfloat16 smem[];
    __nv_bfloat16* sAh = smem;
    __nv_bfloat16* sAl = smem + 2 * SA;
    __nv_bfloat16* sBh = smem + 4 * SA;
    __nv_bfloat16* sBl = smem + 6 * SA;

    const int tid  = threadIdx.x;
    const int lane = tid & 31;
    const int warp = tid >> 5;
    const int wm = warp >> 1;
    const int wn = warp & 1;
    const int rb = blockIdx.x * 128, cb = blockIdx.y * 128;

    const int a_row = lane & 15;
    const int a_k   = (lane >> 4) << 3;
    const int b_n   = (lane & 7) + ((lane >> 4) << 3);
    const int b_k   = lane & 8;

    const unsigned uAh = (unsigned)__cvta_generic_to_shared(sAh);
    const unsigned uAl = (unsigned)__cvta_generic_to_shared(sAl);
    const unsigned uBh = (unsigned)__cvta_generic_to_shared(sBh);
    const unsigned uBl = (unsigned)__cvta_generic_to_shared(sBl);

    float acc[2][8][4];
#pragma unroll
    for (int i = 0; i < 2; i++)
#pragma unroll
        for (int j = 0; j < 8; j++)
#pragma unroll
            for (int q = 0; q < 4; q++) acc[i][j][q] = 0.0f;

    const int NCH = K / KC;

    auto issue = [&](int kc, int st) {
#pragma unroll
        for (int it = 0; it < 2; it++) {
            int i   = tid + it * 256;
            int row = i >> 2;
            int ac  = (i & 3) * 8;
            unsigned doff = (unsigned)((st * SA + row * PITCH + ac) * 2);
            size_t ga = (size_t)(rb + row) * K + kc + ac;
            size_t gb = (size_t)(cb + row) * K + kc + ac;
            cpa16(uAh + doff, Ah + ga);
            if (NPASS == 3) cpa16(uAl + doff, Al + ga);
            cpa16(uBh + doff, Bh + gb);
            cpa16(uBl + doff, Bl + gb);
        }
        cpa_commit();
    };

    issue(0, 0);

    for (int ch = 0; ch < NCH; ch++) {
        cpa_wait0();
        __syncthreads();
        if (ch + 1 < NCH) issue((ch + 1) * KC, (ch + 1) & 1);

        const int st = ch & 1;
#pragma unroll
        for (int s = 0; s < 2; s++) {
            unsigned ah[2][4], al[2][4];
#pragma unroll
            for (int mt = 0; mt < 2; mt++) {
                unsigned offA = (unsigned)(((st * SA) +
                    (wm * 32 + mt * 16 + a_row) * PITCH + s * 16 + a_k) * 2);
                ldsm4(ah[mt][0], ah[mt][1], ah[mt][2], ah[mt][3], uAh + offA);
                if (NPASS == 3)
                    ldsm4(al[mt][0], al[mt][1], al[mt][2], al[mt][3], uAl + offA);
            }
#pragma unroll
            for (int nt = 0; nt < 4; nt++) {
                unsigned offB = (unsigned)(((st * SA) +
                    (wn * 64 + nt * 16 + b_n) * PITCH + s * 16 + b_k) * 2);
                unsigned bh[4], bl[4];
                ldsm4(bh[0], bh[1], bh[2], bh[3], uBh + offB);
                ldsm4(bl[0], bl[1], bl[2], bl[3], uBl + offB);
#pragma unroll
                for (int mt = 0; mt < 2; mt++) {
                    mma16816(acc[mt][nt * 2 + 0], ah[mt], &bh[0]);
                    mma16816(acc[mt][nt * 2 + 0], ah[mt], &bl[0]);
                    if (NPASS == 3) mma16816(acc[mt][nt * 2 + 0], al[mt], &bh[0]);
                    mma16816(acc[mt][nt * 2 + 1], ah[mt], &bh[2]);
                    mma16816(acc[mt][nt * 2 + 1], ah[mt], &bl[2]);
                    if (NPASS == 3) mma16816(acc[mt][nt * 2 + 1], al[mt], &bh[2]);
                }
            }
        }
        __syncthreads();
    }

    if (EPI == 3) {
        // stage z = acc + bias + R into smem (pipeline stages now idle), then LN
        float* zbuf = (float*)smem;      // 128 x ZP fp32 = 67.6 KB < 80 KB
#pragma unroll
        for (int mt = 0; mt < 2; mt++) {
#pragma unroll
            for (int jj = 0; jj < 8; jj++) {
                int lrow0 = wm * 32 + mt * 16 + (lane >> 2);
                int col   = wn * 64 + jj * 8 + ((lane & 3) << 1);
                float2 bi = *(const float2*)&bias[col];
#pragma unroll
                for (int half = 0; half < 2; half++) {
                    int lrow = lrow0 + half * 8;
                    float2 r = *(const float2*)&R[(size_t)(rb + lrow) * Nn + col];
                    zbuf[lrow * ZP + col]     = acc[mt][jj][half * 2 + 0] + bi.x + r.x;
                    zbuf[lrow * ZP + col + 1] = acc[mt][jj][half * 2 + 1] + bi.y + r.y;
                }
            }
        }
        __syncthreads();
        // warp w handles rows w*16 .. w*16+15
        for (int rr = 0; rr < 16; rr++) {
            int lrow = warp * 16 + rr;
            int grow = rb + lrow;
            float4 v = *(const float4*)&zbuf[lrow * ZP + lane * 4];
            float mu = wsum(v.x + v.y + v.z + v.w) * (1.0f / DIM);
            float dx = v.x - mu, dy = v.y - mu, dz = v.z - mu, dw = v.w - mu;
            float var = wsum(dx * dx + dy * dy + dz * dz + dw * dw) * (1.0f / DIM);
            float rstd = rsqrtf(var + LN_EPS);
            float4 g = ((const float4*)ln_g)[lane];
            float4 b = ((const float4*)ln_b)[lane];
            float4 o;
            o.x = dx * rstd * g.x + b.x;  o.y = dy * rstd * g.y + b.y;
            o.z = dz * rstd * g.z + b.z;  o.w = dw * rstd * g.w + b.w;
            if (grow < N_NODES)
                *(float4*)&C[(size_t)grow * DIM + lane * 4] = o;
        }
        return;
    }

#pragma unroll
    for (int mt = 0; mt < 2; mt++) {
#pragma unroll
        for (int jj = 0; jj < 8; jj++) {
            int row0 = rb + wm * 32 + mt * 16 + (lane >> 2);
            int col  = cb + wn * 64 + jj * 8 + ((lane & 3) << 1);
            float2 bi = *(const float2*)&bias[col];
#pragma unroll
            for (int half = 0; half < 2; half++) {
                int row = row0 + half * 8;
                float v0 = acc[mt][jj][half * 2 + 0] + bi.x;
                float v1 = acc[mt][jj][half * 2 + 1] + bi.y;
                if (EPI == 1) {
                    v0 = gelu_exact(v0); v1 = gelu_exact(v1);
                    __nv_bfloat16 h0, h1, l0, l1;
                    hl_split(v0, h0, l0); hl_split(v1, h1, l1);
                    *(__nv_bfloat162*)&Chh[(size_t)row * Nn + col] = __halves2bfloat162(h0, h1);
                    *(__nv_bfloat162*)&Cll[(size_t)row * Nn + col] = __halves2bfloat162(l0, l1);
                } else {
                    *(float2*)&C[(size_t)row * Nn + col] = make_float2(v0, v1);
                }
            }
        }
    }
}

// ================= CSR build ================================================
__global__ void csr_hist(const int* __restrict__ ei)
{
    int e = blockIdx.x * blockDim.x + threadIdx.x;
    if (e < N_EDGES) atomicAdd(&g_cur[ei[N_EDGES + e]], 1);
}
__global__ __launch_bounds__(1024)
void csr_scan1()
{
    int tid = threadIdx.x, lane = tid & 31, warp = tid >> 5;
    int idx = blockIdx.x * 1024 + tid;
    int val = (idx < N_NODES) ? g_cur[idx] : 0;
    int v = val;
#pragma unroll
    for (int o = 1; o < 32; o <<= 1) {
        int t = __shfl_up_sync(0xffffffffu, v, o);
        if (lane >= o) v += t;
    }
    __shared__ int ws[32];
    if (lane == 31) ws[warp] = v;
    __syncthreads();
    if (warp == 0) {
        int w = ws[lane];
#pragma unroll
        for (int o = 1; o < 32; o <<= 1) {
            int t = __shfl_up_sync(0xffffffffu, w, o);
            if (lane >= o) w += t;
        }
        ws[lane] = w;
    }
    __syncthreads();
    int incl = v + (warp ? ws[warp - 1] : 0);
    if (idx < N_NODES) g_off[idx] = incl - val;
    if (tid == 1023) g_bsum[blockIdx.x] = incl;
}
__global__ void csr_scan23(int nblk)
{
    __shared__ int ps[64];
    if (threadIdx.x == 0) {
        int run = 0;
        for (int b = 0; b < nblk; b++) { ps[b] = run; run += g_bsum[b]; }
    }
    __syncthreads();
    int idx = blockIdx.x * blockDim.x + threadIdx.x;
    if (idx < N_NODES) {
        int o = g_off[idx] + ps[idx >> 10];
        g_off[idx] = o;
        g_cur[idx] = o;
    }
    if (idx == 0) g_off[N_NODES] = ETOT;
}
__global__ void csr_scatter(const int* __restrict__ ei)
{
    int id = blockIdx.x * blockDim.x + threadIdx.x;
    if (id < N_NODES) {
        int pos = atomicAdd(&g_cur[id], 1);
        g_csr[pos] = id;
    } else if (id < N_NODES + N_EDGES) {
        int e = id - N_NODES;
        int src = ei[e], dst = ei[N_EDGES + e];
        int pos = atomicAdd(&g_cur[dst], 1);
        g_csr[pos] = src;
    }
}

// ================= fused GAT (R8 exact: pairwise online softmax) ============
__global__ __launch_bounds__(256)
void gat_fused(const float* __restrict__ x, const float* __restrict__ att,
               const float* __restrict__ bias, const float* __restrict__ g1,
               const float* __restrict__ be1)
{
    int node = (blockIdx.x * blockDim.x + threadIdx.x) >> 5;
    int lane = threadIdx.x & 31;
    if (node >= N_NODES) return;

    const float4* xrp = (const float4*)(g_xr + (size_t)node * HD);
    const float4* at4 = (const float4*)att;
    float4 xr4[HEADS], at[HEADS];
#pragma unroll
    for (int h = 0; h < HEADS; h++) {
        xr4[h] = xrp[h * 32 + lane];
        at[h]  = at4[h * 32 + lane];
    }

    float m[HEADS], s[HEADS];
    float4 acc[HEADS];
#pragma unroll
    for (int h = 0; h < HEADS; h++) {
        m[h] = -INFINITY; s[h] = 0.0f;
        acc[h] = make_float4(0.f, 0.f, 0.f, 0.f);
    }

    const int beg = g_off[node], end = g_off[node + 1];
    int j = beg;
    for (; j + 2 <= end; j += 2) {
        int s0 = __ldg(&g_csr[j]);
        int s1 = __ldg(&g_csr[j + 1]);
        const float4* p0 = (const float4*)(g_xl + (size_t)s0 * HD);
        const float4* p1 = (const float4*)(g_xl + (size_t)s1 * HD);
        float4 v0[HEADS], v1[HEADS];
        float  e0[HEADS], e1[HEADS];
#pragma unroll
        for (int h = 0; h < HEADS; h++) {
            v0[h] = __ldg(&p0[h * 32 + lane]);
            v1[h] = __ldg(&p1[h * 32 + lane]);
        }
#pragma unroll
        for (int h = 0; h < HEADS; h++) {
            float4 t = at[h], r = xr4[h];
            float4 a = v0[h], b = v1[h];
            e0[h] = lrelu(a.x + r.x) * t.x + lrelu(a.y + r.y) * t.y
                  + lrelu(a.z + r.z) * t.z + lrelu(a.w + r.w) * t.w;
            e1[h] = lrelu(b.x + r.x) * t.x + lrelu(b.y + r.y) * t.y
                  + lrelu(b.z + r.z) * t.z + lrelu(b.w + r.w) * t.w;
        }
#pragma unroll
        for (int o = 16; o; o >>= 1) {
#pragma unroll
            for (int h = 0; h < HEADS; h++) {
                e0[h] += __shfl_xor_sync(0xffffffffu, e0[h], o);
                e1[h] += __shfl_xor_sync(0xffffffffu, e1[h], o);
            }
        }
#pragma unroll
        for (int h = 0; h < HEADS; h++) {
            float mn = fmaxf(m[h], fmaxf(e0[h], e1[h]));
            float sc = __expf(m[h] - mn);
            float q0 = __expf(e0[h] - mn);
            float q1 = __expf(e1[h] - mn);
            s[h] = s[h] * sc + q0 + q1;
            acc[h].x = acc[h].x * sc + q0 * v0[h].x + q1 * v1[h].x;
            acc[h].y = acc[h].y * sc + q0 * v0[h].y + q1 * v1[h].y;
            acc[h].z = acc[h].z * sc + q0 * v0[h].z + q1 * v1[h].z;
            acc[h].w = acc[h].w * sc + q0 * v0[h].w + q1 * v1[h].w;
            m[h] = mn;
        }
    }
    if (j < end) {
        int s0 = __ldg(&g_csr[j]);
        const float4* p0 = (const float4*)(g_xl + (size_t)s0 * HD);
        float4 v0[HEADS];
        float  e0[HEADS];
#pragma unroll
        for (int h = 0; h < HEADS; h++) {
            v0[h] = __ldg(&p0[h * 32 + lane]);
            float4 t = at[h], r = xr4[h], a = v0[h];
            e0[h] = lrelu(a.x + r.x) * t.x + lrelu(a.y + r.y) * t.y
                  + lrelu(a.z + r.z) * t.z + lrelu(a.w + r.w) * t.w;
        }
#pragma unroll
        for (int o = 16; o; o >>= 1)
#pragma unroll
            for (int h = 0; h < HEADS; h++)
                e0[h] += __shfl_xor_sync(0xffffffffu, e0[h], o);
#pragma unroll
        for (int h = 0; h < HEADS; h++) {
            float mn = fmaxf(m[h], e0[h]);
            float sc = __expf(m[h] - mn);
            float q0 = __expf(e0[h] - mn);
            s[h] = s[h] * sc + q0;
            acc[h].x = acc[h].x * sc + q0 * v0[h].x;
            acc[h].y = acc[h].y * sc + q0 * v0[h].y;
            acc[h].z = acc[h].z * sc + q0 * v0[h].z;
            acc[h].w = acc[h].w * sc + q0 * v0[h].w;
            m[h] = mn;
        }
    }

    float4 o4 = make_float4(0.f, 0.f, 0.f, 0.f);
#pragma unroll
    for (int h = 0; h < HEADS; h++) {
        float inv = 0.25f / (s[h] + 1e-16f);
        o4.x += acc[h].x * inv; o4.y += acc[h].y * inv;
        o4.z += acc[h].z * inv; o4.w += acc[h].w * inv;
    }
    float4 xb = ((const float4*)x)[(size_t)node * 32 + lane];
    float4 b4 = ((const float4*)bias)[lane];
    float4 v;
    v.x = xb.x + o4.x + b4.x;  v.y = xb.y + o4.y + b4.y;
    v.z = xb.z + o4.z + b4.z;  v.w = xb.w + o4.w + b4.w;

    float mu = wsum(v.x + v.y + v.z + v.w) * (1.0f / DIM);
    float dx = v.x - mu, dy = v.y - mu, dz = v.z - mu, dw = v.w - mu;
    float var = wsum(dx * dx + dy * dy + dz * dz + dw * dw) * (1.0f / DIM);
    float rstd = rsqrtf(var + LN_EPS);
    float4 g = ((const float4*)g1)[lane];
    float4 b = ((const float4*)be1)[lane];
    float4 o;
    o.x = dx * rstd * g.x + b.x;  o.y = dy * rstd * g.y + b.y;
    o.z = dz * rstd * g.z + b.z;  o.w = dw * rstd * g.w + b.w;
    ((float4*)g_y1)[(size_t)node * 32 + lane] = o;

    __nv_bfloat16 h0, h1, h2, h3, l0, l1, l2, l3;
    hl_split(o.x, h0, l0); hl_split(o.y, h1, l1);
    hl_split(o.z, h2, l2); hl_split(o.w, h3, l3);
    size_t base = (size_t)node * 64 + lane * 2;
    ((__nv_bfloat162*)g_y1h)[base]     = __halves2bfloat162(h0, h1);
    ((__nv_bfloat162*)g_y1h)[base + 1] = __halves2bfloat162(h2, h3);
    ((__nv_bfloat162*)g_y1l)[base]     = __halves2bfloat162(l0, l1);
    ((__nv_bfloat162*)g_y1l)[base + 1] = __halves2bfloat162(l2, l3);
}

// ---------------- launch -----------------------------------------------------
extern "C" void kernel_launch(void* const* d_in, const int* in_sizes, int n_in,
                              void* d_out, int out_size)
{
    const float* x    = (const float*)d_in[0];
    const int*   ei   = (const int*)d_in[1];
    const float* Wl   = (const float*)d_in[2];
    const float* bl   = (const float*)d_in[3];
    const float* Wr   = (const float*)d_in[4];
    const float* br   = (const float*)d_in[5];
    const float* att  = (const float*)d_in[6];
    const float* bias = (const float*)d_in[7];
    const float* g1   = (const float*)d_in[8];
    const float* be1  = (const float*)d_in[9];
    const float* W1   = (const float*)d_in[10];
    const float* b1   = (const float*)d_in[11];
    const float* W2   = (const float*)d_in[12];
    const float* b2   = (const float*)d_in[13];
    const float* g2   = (const float*)d_in[14];
    const float* be2  = (const float*)d_in[15];
    float* out = (float*)d_out;

    float *p_xl, *p_xr, *p_y1;
    __nv_bfloat16 *p_xh, *p_xlo, *p_y1h, *p_y1l, *p_mh, *p_ml;
    __nv_bfloat16 *p_Wlh, *p_Wll, *p_Wrh, *p_Wrl, *p_W1h, *p_W1l, *p_W2h, *p_W2l;
    cudaGetSymbolAddress((void**)&p_xl,  g_xl);
    cudaGetSymbolAddress((void**)&p_xr,  g_xr);
    cudaGetSymbolAddress((void**)&p_y1,  g_y1);
    cudaGetSymbolAddress((void**)&p_xh,  g_xh);
    cudaGetSymbolAddress((void**)&p_xlo, g_xlo);
    cudaGetSymbolAddress((void**)&p_y1h, g_y1h);
    cudaGetSymbolAddress((void**)&p_y1l, g_y1l);
    cudaGetSymbolAddress((void**)&p_mh,  g_mh);
    cudaGetSymbolAddress((void**)&p_ml,  g_ml);
    cudaGetSymbolAddress((void**)&p_Wlh, g_Wlh);
    cudaGetSymbolAddress((void**)&p_Wll, g_Wll);
    cudaGetSymbolAddress((void**)&p_Wrh, g_Wrh);
    cudaGetSymbolAddress((void**)&p_Wrl, g_Wrl);
    cudaGetSymbolAddress((void**)&p_W1h, g_W1h);
    cudaGetSymbolAddress((void**)&p_W1l, g_W1l);
    cudaGetSymbolAddress((void**)&p_W2h, g_W2h);
    cudaGetSymbolAddress((void**)&p_W2l, g_W2l);

    const int SMEM = 8 * SA * 2;   // 81920 bytes
    cudaFuncSetAttribute(gemm_bf16<3, 0>, cudaFuncAttributeMaxDynamicSharedMemorySize, SMEM);
    cudaFuncSetAttribute(gemm_bf16<2, 0>, cudaFuncAttributeMaxDynamicSharedMemorySize, SMEM);
    cudaFuncSetAttribute(gemm_bf16<3, 1>, cudaFuncAttributeMaxDynamicSharedMemorySize, SMEM);
    cudaFuncSetAttribute(gemm_bf16<3, 3>, cudaFuncAttributeMaxDynamicSharedMemorySize, SMEM);

    const int MB = M_PAD / 128;                 // 391
    const int SNBLK = (N_NODES + 1023) / 1024;  // 49

    prep<<<(NPREP + 255) / 256, 256>>>(x, Wl, Wr, W1, W2);

    csr_hist<<<(N_EDGES + 255) / 256, 256>>>(ei);
    csr_scan1<<<SNBLK, 1024>>>();
    csr_scan23<<<(N_NODES + 255) / 256, 256>>>(SNBLK);
    csr_scatter<<<(N_NODES + N_EDGES + 255) / 256, 256>>>(ei);

    // xl = x @ Wl^T + bl  (3-pass: feeds aggregation)
    gemm_bf16<3, 0><<<dim3(MB, HD / 128), 256, SMEM>>>(p_xh, p_xlo, p_Wlh, p_Wll, bl,
                                                       nullptr, p_xl, nullptr, nullptr,
                                                       nullptr, nullptr, HD, DIM);
    // xr = x @ Wr^T + br  (2-pass: logits only)
    gemm_bf16<2, 0><<<dim3(MB, HD / 128), 256, SMEM>>>(p_xh, nullptr, p_Wrh, p_Wrl, br,
                                                       nullptr, p_xr, nullptr, nullptr,
                                                       nullptr, nullptr, HD, DIM);

    gat_fused<<<(N_NODES * 32 + 255) / 256, 256>>>(x, att, bias, g1, be1);

    // mid = gelu(y1 @ W1^T + b1) -> bf16 hi/lo
    gemm_bf16<3, 1><<<dim3(MB, (2 * DIM) / 128), 256, SMEM>>>(p_y1h, p_y1l, p_W1h, p_W1l, b1,
                                                              nullptr, nullptr, p_mh, p_ml,
                                                              nullptr, nullptr, 2 * DIM, DIM);
    // out = LN2(mid @ W2^T + b2 + y1)  (fused epilogue, writes final output)
    gemm_bf16<3, 3><<<dim3(MB, 1), 256, SMEM>>>(p_mh, p_ml, p_W2h, p_W2l, b2,
                                                p_y1, out, nullptr, nullptr,
                                                g2, be2, DIM, 2 * DIM);
}